// round 14
// baseline (speedup 1.0000x reference)
#include <cuda_runtime.h>
#include <cuda_fp16.h>
#include <cstdint>

#define BB   16
#define CI   64
#define CO   64
#define HHH  128
#define WWW  128
#define NN   8

#define XBU 6528             // uint32 per x buffer: 6 ri x 8 ci2 x 136 (half2)
#define WBU 4608             // uint32 per W buffer: 9 t x 4 mt x 32 lanes x 4
#define SMEM_BYTES (2 * (XBU + WBU) * 4)   // 89,088 (1 CTA/SM; L1 ~139KB)
#define NTILES (32 * BB)     // 32 h-quads x 16 batches

// ---------------------------------------------------------------------------
// Device scratch (no allocation allowed)
// ---------------------------------------------------------------------------
__device__ float g_beff[BB * CO];
// fragment-packed fp16 filters: [b][cb=4][t=9][mt=4][lane=32][4 regs] (half2)
__device__ uint32_t g_wefft[BB * 4 * 9 * 4 * 32 * 4];

// ---------------------------------------------------------------------------
// helpers
// ---------------------------------------------------------------------------
__device__ __forceinline__ uint32_t smem_u32(const void* p) {
    uint32_t a;
    asm("{ .reg .u64 t; cvta.to.shared.u64 t, %1; cvt.u32.u64 %0, t; }"
        : "=r"(a) : "l"(p));
    return a;
}
__device__ __forceinline__ void cpa16(uint32_t dst, const void* src) {
    asm volatile("cp.async.cg.shared.global [%0], [%1], 16;"
                 :: "r"(dst), "l"(src) : "memory");
}
__device__ __forceinline__ uint32_t h2pack(float lo, float hi) {
    uint32_t r;
    asm("cvt.rn.f16x2.f32 %0, %2, %1;" : "=r"(r) : "f"(lo), "f"(hi));
    return r;
}
__device__ __forceinline__ void mma16(float* d, const uint32_t* a, uint32_t b0, uint32_t b1) {
    asm volatile(
        "mma.sync.aligned.m16n8k16.row.col.f32.f16.f16.f32 "
        "{%0,%1,%2,%3}, {%4,%5,%6,%7}, {%8,%9}, {%0,%1,%2,%3};"
        : "+f"(d[0]), "+f"(d[1]), "+f"(d[2]), "+f"(d[3])
        : "r"(a[0]), "r"(a[1]), "r"(a[2]), "r"(a[3]), "r"(b0), "r"(b1));
}

// ---------------------------------------------------------------------------
// Kernel 1: effective filters, FRAGMENT-PACKED fp16 + bias. Warp-coalesced.
// warp task = blockIdx.x*8 + warpid in [0,128): co = task>>1, ci = (task&1)*32+lane.
// ---------------------------------------------------------------------------
__global__ void k_weff(const float* __restrict__ filt_w,
                       const float* __restrict__ cond,
                       const float* __restrict__ sel_w,
                       const float* __restrict__ sel_b,
                       const float* __restrict__ filt_b) {
    __shared__ float sw[NN];
    int b = blockIdx.y;
    int tid = threadIdx.x;
    int lane = tid & 31;
    int warp = tid >> 5;

    if (tid < 32) {
        int n = lane & 7;
        float logit = sel_b[n];
        #pragma unroll 8
        for (int k = 0; k < CI; k++)
            logit += cond[b * CI + k] * sel_w[n * CI + k];
        float m = logit;
        #pragma unroll
        for (int o = 4; o; o >>= 1) m = fmaxf(m, __shfl_xor_sync(0xffffffffu, m, o));
        float e = __expf(logit - m);
        float s = e;
        #pragma unroll
        for (int o = 4; o; o >>= 1) s += __shfl_xor_sync(0xffffffffu, s, o);
        if (lane < 8) sw[lane] = e / s;
    }
    __syncthreads();

    float w[NN];
    #pragma unroll
    for (int n = 0; n < NN; n++) w[n] = sw[n];

    int task = blockIdx.x * 8 + warp;      // 0..127
    int co  = task >> 1;
    int ci  = (task & 1) * 32 + lane;

    float acc[9];
    #pragma unroll
    for (int t = 0; t < 9; t++) acc[t] = 0.f;
    #pragma unroll
    for (int n = 0; n < NN; n++) {
        const float* fp = filt_w + ((size_t)(n * CO + co) * CI + ci) * 9;
        #pragma unroll
        for (int t = 0; t < 9; t++) acc[t] += w[n] * __ldg(fp + t);
    }

    uint32_t* outb = g_wefft + (size_t)b * 18432;
    int cq = ci & 15;
    int cb = ci >> 4;
    int lq = (cq & 7) >> 1;
    int e1 = cq >> 3;
    int mt = co >> 4;
    int lr = (co & 15) & 7;
    int e0 = (co & 15) >> 3;
    int fl = lr * 4 + lq;
    #pragma unroll
    for (int t = 0; t < 9; t++) {
        float hi = __shfl_down_sync(0xffffffffu, acc[t], 1);
        if (!(lane & 1)) {
            int idx = ((cb * 9 + t) * 4 + mt) * 128 + fl * 4 + (e1 * 2 + e0);
            outb[idx] = h2pack(acc[t], hi);
        }
    }

    if (blockIdx.x == 0 && tid < CO) {
        float sb = 0.f;
        #pragma unroll
        for (int n = 0; n < NN; n++) sb += w[n] * filt_b[n * CO + tid];
        g_beff[b * CO + tid] = sb;
    }
}

// ---------------------------------------------------------------------------
// Kernel 2: fp16 mma.sync conv — FAT WARPS (M=64co x N=64px), 8 warps/CTA,
// 4-row tiles, persistent. warp: hl = warp>>1 (h row 0..3), colhalf = warp&1.
// Tile = (h-quad, batch); 4 ci-blocks of 16, x double-buffered in smem
// (6 rows incl. halo), W double-buffered via cp.async.
// ---------------------------------------------------------------------------
__global__ __launch_bounds__(256, 1) void k_conv(const float* __restrict__ x,
                                                 float* __restrict__ out) {
    extern __shared__ uint32_t smu[];
    uint32_t* SX = smu;               // [2][XBU]
    uint32_t* SW = smu + 2 * XBU;     // [2][WBU]
    uint32_t sw_u = smem_u32(SW);

    int tid  = threadIdx.x;
    int warp = tid >> 5;
    int lane = tid & 31;
    int lq = lane & 3, lr = lane >> 2;
    int hl   = warp >> 1;             // h row within quad (0..3)
    int colb = (warp & 1) * 64;       // col half
    int c4 = tid & 31, ci2s = (tid >> 5) & 7;
    int xoff = lq * 136 + colb + 3 + lr;

    // halo zero columns (col -1 at idx 3, col 128 at idx 132), both buffers.
    // 2 sides x 6 ri x 8 ci2 x 2 buf = 192 slots; never overwritten afterwards.
    if (tid < 192) {
        int bf = tid >= 96;
        int j  = tid - bf * 96;
        int sd = j & 1, ci2 = (j >> 1) & 7, ri = j >> 4;   // ri 0..5
        SX[bf * XBU + ri * 1088 + ci2 * 136 + (sd ? 132 : 3)] = 0u;
    }

    uint4 rx[6];
    // x staging: 1536 uint4 chunks, 6 per thread: ri = k, ci2 = (tid>>5)&7.
    #define LDGX(cb)                                                            \
    {                                                                           \
        _Pragma("unroll")                                                       \
        for (int k = 0; k < 6; k++) {                                           \
            int gh = h0 - 1 + k;                                                \
            float4 va = make_float4(0.f, 0.f, 0.f, 0.f), vb = va;               \
            if ((unsigned)gh < 128u) {                                          \
                const float* p = xb + ((size_t)((cb) * 16 + 2 * ci2s) * HHH + gh) * WWW + c4 * 4; \
                va = __ldg((const float4*)p);                                   \
                vb = __ldg((const float4*)(p + HHH * WWW));                     \
            }                                                                   \
            rx[k].x = h2pack(va.x, vb.x);                                       \
            rx[k].y = h2pack(va.y, vb.y);                                       \
            rx[k].z = h2pack(va.z, vb.z);                                       \
            rx[k].w = h2pack(va.w, vb.w);                                       \
        }                                                                       \
    }
    #define STSX(bf)                                                            \
    {                                                                           \
        _Pragma("unroll")                                                       \
        for (int k = 0; k < 6; k++)                                             \
            *(uint4*)(SX + (bf) * XBU + k * 1088 + ci2s * 136 + 4 + c4 * 4) = rx[k]; \
    }
    #define STGW(cb, bf)                                                        \
    {                                                                           \
        _Pragma("unroll")                                                       \
        for (int k = 0; k < 5; k++) {                                           \
            int c = tid + 256 * k;                                              \
            if (c < 1152)                                                       \
                cpa16(sw_u + ((bf) * WBU + c * 4) * 4,                          \
                      wbg + (size_t)(cb) * 4608 + c * 4);                       \
        }                                                                       \
        asm volatile("cp.async.commit_group;" ::: "memory");                    \
    }

    for (int tile = blockIdx.x; tile < NTILES; tile += gridDim.x) {
        int hp = tile & 31;
        int b  = tile >> 5;
        int h0 = hp * 4;
        const float* xb  = x + (size_t)b * CI * HHH * WWW;
        const uint32_t* wbg = g_wefft + (size_t)b * 18432;

        // accumulators initialized with bias: [mt=4][nt=8][4]
        float d[4][8][4];
        #pragma unroll
        for (int mt = 0; mt < 4; mt++) {
            float bz0 = g_beff[b * CO + mt * 16 + lr];
            float bz1 = g_beff[b * CO + mt * 16 + lr + 8];
            #pragma unroll
            for (int nt = 0; nt < 8; nt++) {
                d[mt][nt][0] = bz0; d[mt][nt][1] = bz0;
                d[mt][nt][2] = bz1; d[mt][nt][3] = bz1;
            }
        }

        // prologue: fill buffer 0
        LDGX(0);
        STGW(0, 0);
        STSX(0);
        asm volatile("cp.async.wait_group 0;" ::: "memory");
        __syncthreads();

        #pragma unroll 1
        for (int cb = 0; cb < 4; cb++) {
            int buf = cb & 1;
            if (cb < 3) {
                LDGX(cb + 1);
                STGW(cb + 1, buf ^ 1);
            }

            const uint32_t* bxu = SX + buf * XBU;
            const uint4*    bw4 = (const uint4*)(SW + buf * WBU);

            #pragma unroll
            for (int kh = 0; kh < 3; kh++) {
                int ri = hl + kh;
                #pragma unroll
                for (int kw = 0; kw < 3; kw++) {
                    int t = kh * 3 + kw;
                    uint32_t a[4][4];
                    #pragma unroll
                    for (int mt = 0; mt < 4; mt++) {
                        uint4 v = bw4[(t * 4 + mt) * 32 + lane];
                        a[mt][0] = v.x; a[mt][1] = v.y; a[mt][2] = v.z; a[mt][3] = v.w;
                    }
                    const uint32_t* xp = bxu + ri * 1088 + xoff + kw;
                    #pragma unroll
                    for (int nt = 0; nt < 8; nt++) {
                        uint32_t b0 = xp[nt * 8];              // ci2 = lq
                        uint32_t b1 = xp[4 * 136 + nt * 8];    // ci2 = lq + 4
                        #pragma unroll
                        for (int mt = 0; mt < 4; mt++)
                            mma16(d[mt][nt], a[mt], b0, b1);
                    }
                }
            }

            if (cb < 3) {
                STSX(buf ^ 1);
                asm volatile("cp.async.wait_group 0;" ::: "memory");
                __syncthreads();
            }
        }

        // epilogue: store (bias already folded into d)
        int h = h0 + hl;
        #pragma unroll
        for (int mt = 0; mt < 4; mt++) {
            int co = mt * 16 + lr;
            float* r0 = out + (((size_t)(b * CO + co) * HHH + h) * WWW);
            float* r1 = out + (((size_t)(b * CO + co + 8) * HHH + h) * WWW);
            #pragma unroll
            for (int nt = 0; nt < 8; nt++) {
                int col = colb + nt * 8 + 2 * lq;
                *(float2*)(r0 + col) = make_float2(d[mt][nt][0], d[mt][nt][1]);
                *(float2*)(r1 + col) = make_float2(d[mt][nt][2], d[mt][nt][3]);
            }
        }
        // no barrier needed between tiles: next prologue writes buffer 0 only
        // and publishes it with its own __syncthreads.
    }
}

// ---------------------------------------------------------------------------
extern "C" void kernel_launch(void* const* d_in, const int* in_sizes, int n_in,
                              void* d_out, int out_size) {
    const float* x      = (const float*)d_in[0];   // [16,64,128,128]
    const float* cond   = (const float*)d_in[1];   // [16,64]
    const float* filt_w = (const float*)d_in[2];   // [8,64,64,3,3]
    const float* filt_b = (const float*)d_in[3];   // [8,64]
    const float* sel_w  = (const float*)d_in[4];   // [8,64]
    const float* sel_b  = (const float*)d_in[5];   // [8]
    float* out = (float*)d_out;                    // [16,64,128,128]

    cudaFuncSetAttribute(k_conv, cudaFuncAttributeMaxDynamicSharedMemorySize, SMEM_BYTES);

    int nsm = 148;
    cudaDeviceGetAttribute(&nsm, cudaDevAttrMultiProcessorCount, 0);

    dim3 g1(16, BB);                               // 128 warp-tasks / 8 per block
    k_weff<<<g1, 256>>>(filt_w, cond, sel_w, sel_b, filt_b);

    int g2 = nsm;                                  // persistent: 1 CTA per SM
    if (g2 > NTILES) g2 = NTILES;
    k_conv<<<g2, 256, SMEM_BYTES>>>(x, out);
}

// round 15
// speedup vs baseline: 1.1756x; 1.1756x over previous
#include <cuda_runtime.h>
#include <cuda_fp16.h>
#include <cstdint>

#define BB   16
#define CI   64
#define CO   64
#define HHH  128
#define WWW  128
#define NN   8

#define XBU 4352             // uint32 per x buffer: 4 ri x 8 ci2 x 136 (half2)
#define WBU 4608             // uint32 per W buffer: 9 t x 4 mt x 32 lanes x 4
#define SMEM_BYTES (2 * (XBU + WBU) * 4)   // 71,680 (2 CTAs/SM, L1 ~85KB)
#define NTILES (64 * BB)     // 64 h-pairs x 16 batches

// ---------------------------------------------------------------------------
// Device scratch (no allocation allowed)
// ---------------------------------------------------------------------------
__device__ float g_beff[BB * CO];
// fragment-packed fp16 filters: [b][cb=4][t=9][mt=4][lane=32][4 regs] (half2)
__device__ uint32_t g_wefft[BB * 4 * 9 * 4 * 32 * 4];
__device__ unsigned g_tilectr;     // work-stealing counter (reset by k_weff)

// ---------------------------------------------------------------------------
// helpers
// ---------------------------------------------------------------------------
__device__ __forceinline__ uint32_t smem_u32(const void* p) {
    uint32_t a;
    asm("{ .reg .u64 t; cvta.to.shared.u64 t, %1; cvt.u32.u64 %0, t; }"
        : "=r"(a) : "l"(p));
    return a;
}
__device__ __forceinline__ void cpa16(uint32_t dst, const void* src) {
    asm volatile("cp.async.cg.shared.global [%0], [%1], 16;"
                 :: "r"(dst), "l"(src) : "memory");
}
__device__ __forceinline__ uint32_t h2pack(float lo, float hi) {
    uint32_t r;
    asm("cvt.rn.f16x2.f32 %0, %2, %1;" : "=r"(r) : "f"(lo), "f"(hi));
    return r;
}
__device__ __forceinline__ void mma16(float* d, const uint32_t* a, uint32_t b0, uint32_t b1) {
    asm volatile(
        "mma.sync.aligned.m16n8k16.row.col.f32.f16.f16.f32 "
        "{%0,%1,%2,%3}, {%4,%5,%6,%7}, {%8,%9}, {%0,%1,%2,%3};"
        : "+f"(d[0]), "+f"(d[1]), "+f"(d[2]), "+f"(d[3])
        : "r"(a[0]), "r"(a[1]), "r"(a[2]), "r"(a[3]), "r"(b0), "r"(b1));
}

// ---------------------------------------------------------------------------
// Kernel 1: effective filters, FRAGMENT-PACKED fp16 + bias. Warp-coalesced.
// Also resets the work-stealing counter for k_conv (same-stream ordering).
// ---------------------------------------------------------------------------
__global__ void k_weff(const float* __restrict__ filt_w,
                       const float* __restrict__ cond,
                       const float* __restrict__ sel_w,
                       const float* __restrict__ sel_b,
                       const float* __restrict__ filt_b,
                       unsigned nconv) {
    __shared__ float sw[NN];
    int b = blockIdx.y;
    int tid = threadIdx.x;
    int lane = tid & 31;
    int warp = tid >> 5;

    if (blockIdx.x == 0 && b == 0 && tid == 0) g_tilectr = nconv;

    if (tid < 32) {
        int n = lane & 7;
        float logit = sel_b[n];
        #pragma unroll 8
        for (int k = 0; k < CI; k++)
            logit += cond[b * CI + k] * sel_w[n * CI + k];
        float m = logit;
        #pragma unroll
        for (int o = 4; o; o >>= 1) m = fmaxf(m, __shfl_xor_sync(0xffffffffu, m, o));
        float e = __expf(logit - m);
        float s = e;
        #pragma unroll
        for (int o = 4; o; o >>= 1) s += __shfl_xor_sync(0xffffffffu, s, o);
        if (lane < 8) sw[lane] = e / s;
    }
    __syncthreads();

    float w[NN];
    #pragma unroll
    for (int n = 0; n < NN; n++) w[n] = sw[n];

    int task = blockIdx.x * 8 + warp;      // 0..127
    int co  = task >> 1;
    int ci  = (task & 1) * 32 + lane;

    float acc[9];
    #pragma unroll
    for (int t = 0; t < 9; t++) acc[t] = 0.f;
    #pragma unroll
    for (int n = 0; n < NN; n++) {
        const float* fp = filt_w + ((size_t)(n * CO + co) * CI + ci) * 9;
        #pragma unroll
        for (int t = 0; t < 9; t++) acc[t] += w[n] * __ldg(fp + t);
    }

    uint32_t* outb = g_wefft + (size_t)b * 18432;
    int cq = ci & 15;
    int cb = ci >> 4;
    int lq = (cq & 7) >> 1;
    int e1 = cq >> 3;
    int mt = co >> 4;
    int lr = (co & 15) & 7;
    int e0 = (co & 15) >> 3;
    int fl = lr * 4 + lq;
    #pragma unroll
    for (int t = 0; t < 9; t++) {
        float hi = __shfl_down_sync(0xffffffffu, acc[t], 1);
        if (!(lane & 1)) {
            int idx = ((cb * 9 + t) * 4 + mt) * 128 + fl * 4 + (e1 * 2 + e0);
            outb[idx] = h2pack(acc[t], hi);
        }
    }

    if (blockIdx.x == 0 && tid < CO) {
        float sb = 0.f;
        #pragma unroll
        for (int n = 0; n < NN; n++) sb += w[n] * filt_b[n * CO + tid];
        g_beff[b * CO + tid] = sb;
    }
}

// ---------------------------------------------------------------------------
// Kernel 2: fp16 mma.sync conv — persistent + WORK-STEALING + cross-tile
// prefetch. Tile = (h-pair, batch). 256 threads, 8 thin warps
// (M=64co x N=32px each). 4 ci-blocks of 16, x+W double-buffered.
// Next tile is stolen at cb2 (atomicAdd), published by the cb2-end barrier;
// during cb3's compute the next tile's cb0 (x + W) is prefetched into the
// free buffer 0, so steady-state tiles start with only wait+barrier.
// ---------------------------------------------------------------------------
__global__ __launch_bounds__(256, 2) void k_conv(const float* __restrict__ x,
                                                 float* __restrict__ out) {
    extern __shared__ uint32_t smu[];
    uint32_t* SX = smu;               // [2][XBU]
    uint32_t* SW = smu + 2 * XBU;     // [2][WBU]
    uint32_t sw_u = smem_u32(SW);
    __shared__ int s_next;

    int tid  = threadIdx.x;
    int warp = tid >> 5;
    int lane = tid & 31;
    int lq = lane & 3, lr = lane >> 2;
    int hl   = warp >> 2;             // h row within pair
    int colb = (warp & 3) * 32;       // col quarter
    int c4 = tid & 31, ci2s = (tid >> 5) & 7;
    int xoff = lq * 136 + colb + 3 + lr;

    // halo zero columns (col -1 at idx 3, col 128 at idx 132), both buffers;
    // never overwritten afterwards.
    if (tid < 128) {
        int sd = tid & 1, ci2 = (tid >> 1) & 7, ri = (tid >> 4) & 3, bf = tid >> 6;
        SX[bf * XBU + ri * 1088 + ci2 * 136 + (sd ? 132 : 3)] = 0u;
    }

    uint4 rx[4];
    #define LDGX(cb, XBP, H0P)                                                  \
    {                                                                           \
        _Pragma("unroll")                                                       \
        for (int k = 0; k < 4; k++) {                                           \
            int gh = (H0P) - 1 + k;                                             \
            float4 va = make_float4(0.f, 0.f, 0.f, 0.f), vb = va;               \
            if ((unsigned)gh < 128u) {                                          \
                const float* p = (XBP) + ((size_t)((cb) * 16 + 2 * ci2s) * HHH + gh) * WWW + c4 * 4; \
                va = __ldg((const float4*)p);                                   \
                vb = __ldg((const float4*)(p + HHH * WWW));                     \
            }                                                                   \
            rx[k].x = h2pack(va.x, vb.x);                                       \
            rx[k].y = h2pack(va.y, vb.y);                                       \
            rx[k].z = h2pack(va.z, vb.z);                                       \
            rx[k].w = h2pack(va.w, vb.w);                                       \
        }                                                                       \
    }
    #define STSX(bf)                                                            \
    {                                                                           \
        _Pragma("unroll")                                                       \
        for (int k = 0; k < 4; k++)                                             \
            *(uint4*)(SX + (bf) * XBU + k * 1088 + ci2s * 136 + 4 + c4 * 4) = rx[k]; \
    }
    #define STGW(cb, bf, WBGP)                                                  \
    {                                                                           \
        _Pragma("unroll")                                                       \
        for (int k = 0; k < 5; k++) {                                           \
            int c = tid + 256 * k;                                              \
            if (c < 1152)                                                       \
                cpa16(sw_u + ((bf) * WBU + c * 4) * 4,                          \
                      (WBGP) + (size_t)(cb) * 4608 + c * 4);                    \
        }                                                                       \
        asm volatile("cp.async.commit_group;" ::: "memory");                    \
    }

    int tile = blockIdx.x;
    bool have_pre = false;

    while (tile < NTILES) {
        int hp = tile & 63;
        int b  = tile >> 6;
        int h0 = hp * 2;
        const float* xb  = x + (size_t)b * CI * HHH * WWW;
        const uint32_t* wbg = g_wefft + (size_t)b * 18432;

        // accumulators initialized with bias: [mt=4][nt=4][4]
        float d[4][4][4];
        #pragma unroll
        for (int mt = 0; mt < 4; mt++) {
            float bz0 = g_beff[b * CO + mt * 16 + lr];
            float bz1 = g_beff[b * CO + mt * 16 + lr + 8];
            #pragma unroll
            for (int nt = 0; nt < 4; nt++) {
                d[mt][nt][0] = bz0; d[mt][nt][1] = bz0;
                d[mt][nt][2] = bz1; d[mt][nt][3] = bz1;
            }
        }

        if (!have_pre) {          // first tile only: exposed prologue
            LDGX(0, xb, h0);
            STGW(0, 0, wbg);
            STSX(0);
        }
        asm volatile("cp.async.wait_group 0;" ::: "memory");
        __syncthreads();          // publishes buffer 0 (x + W)

        bool more = false;

        #pragma unroll 1
        for (int cb = 0; cb < 4; cb++) {
            int buf = cb & 1;

            if (cb == 2 && tid == 0)
                s_next = (int)atomicAdd(&g_tilectr, 1u);

            if (cb < 3) {
                LDGX(cb + 1, xb, h0);
                STGW(cb + 1, buf ^ 1, wbg);
            } else {
                int nt2 = s_next;                 // safe: cb2-end barrier passed
                more = nt2 < NTILES;
                tile = nt2;
                if (more) {
                    int nb = nt2 >> 6, nh0 = (nt2 & 63) * 2;
                    const float* nxb = x + (size_t)nb * CI * HHH * WWW;
                    const uint32_t* nwbg = g_wefft + (size_t)nb * 18432;
                    LDGX(0, nxb, nh0);            // prefetch next tile cb0
                    STGW(0, 0, nwbg);
                }
            }

            const uint32_t* bxu = SX + buf * XBU;
            const uint4*    bw4 = (const uint4*)(SW + buf * WBU);

            #pragma unroll
            for (int kh = 0; kh < 3; kh++) {
                int ri = hl + kh;
                #pragma unroll
                for (int kw = 0; kw < 3; kw++) {
                    int t = kh * 3 + kw;
                    uint32_t a[4][4];
                    #pragma unroll
                    for (int mt = 0; mt < 4; mt++) {
                        uint4 v = bw4[(t * 4 + mt) * 32 + lane];
                        a[mt][0] = v.x; a[mt][1] = v.y; a[mt][2] = v.z; a[mt][3] = v.w;
                    }
                    const uint32_t* xp = bxu + ri * 1088 + xoff + kw;
                    #pragma unroll
                    for (int nt = 0; nt < 4; nt++) {
                        uint32_t b0 = xp[nt * 8];              // ci2 = lq
                        uint32_t b1 = xp[4 * 136 + nt * 8];    // ci2 = lq + 4
                        #pragma unroll
                        for (int mt = 0; mt < 4; mt++)
                            mma16(d[mt][nt], a[mt], b0, b1);
                    }
                }
            }

            if (cb < 3) {
                STSX(buf ^ 1);
                asm volatile("cp.async.wait_group 0;" ::: "memory");
                __syncthreads();
            } else if (more) {
                STSX(0);          // buffer 0 idle since cb2-end barrier
            }
        }

        // epilogue: store (bias already folded into d)
        int h = h0 + hl;
        #pragma unroll
        for (int mt = 0; mt < 4; mt++) {
            int co = mt * 16 + lr;
            float* r0 = out + (((size_t)(b * CO + co) * HHH + h) * WWW);
            float* r1 = out + (((size_t)(b * CO + co + 8) * HHH + h) * WWW);
            #pragma unroll
            for (int nt = 0; nt < 4; nt++) {
                int col = colb + nt * 8 + 2 * lq;
                *(float2*)(r0 + col) = make_float2(d[mt][nt][0], d[mt][nt][1]);
                *(float2*)(r1 + col) = make_float2(d[mt][nt][2], d[mt][nt][3]);
            }
        }

        have_pre = true;          // next tile's buffer 0 already in flight
    }
}

// ---------------------------------------------------------------------------
extern "C" void kernel_launch(void* const* d_in, const int* in_sizes, int n_in,
                              void* d_out, int out_size) {
    const float* x      = (const float*)d_in[0];   // [16,64,128,128]
    const float* cond   = (const float*)d_in[1];   // [16,64]
    const float* filt_w = (const float*)d_in[2];   // [8,64,64,3,3]
    const float* filt_b = (const float*)d_in[3];   // [8,64]
    const float* sel_w  = (const float*)d_in[4];   // [8,64]
    const float* sel_b  = (const float*)d_in[5];   // [8]
    float* out = (float*)d_out;                    // [16,64,128,128]

    cudaFuncSetAttribute(k_conv, cudaFuncAttributeMaxDynamicSharedMemorySize, SMEM_BYTES);

    int nsm = 148;
    cudaDeviceGetAttribute(&nsm, cudaDevAttrMultiProcessorCount, 0);
    int g2 = 2 * nsm;                              // persistent: 2 CTAs per SM
    if (g2 > NTILES) g2 = NTILES;

    dim3 g1(16, BB);                               // 128 warp-tasks / 8 per block
    k_weff<<<g1, 256>>>(filt_w, cond, sel_w, sel_b, filt_b, (unsigned)g2);

    k_conv<<<g2, 256, SMEM_BYTES>>>(x, out);
}